// round 11
// baseline (speedup 1.0000x reference)
#include <cuda_runtime.h>
#include <cuda_fp16.h>

#define N_NODES 100000
#define N_EDGES 500000
#define IN_DIM 16
#define HEADS 4
#define OUT_DIM 128
#define HC 512           // HEADS*OUT_DIM
#define NEG 0.2f

// Scratch (device globals: allocation-free per harness rules)
// x_l / x_r stored HEAD-MAJOR: [h][node][128] halves.
__device__ __half g_xl[(size_t)N_NODES * HC];    // 102.4 MB
__device__ __half g_xr[(size_t)N_NODES * HC];    // 102.4 MB
__device__ float  g_ex[(size_t)N_EDGES * HEADS]; // 8 MB, [slot][h]
__device__ float  g_y[(size_t)N_NODES * 64];     // normalized alpha-weighted X sums
__device__ float  g_gate[(size_t)N_NODES * HEADS];
__device__ int    g_counts[N_NODES];
__device__ int    g_row[N_NODES + 1];
__device__ int    g_cursor[N_NODES];
__device__ int    g_srcs[N_EDGES];               // CSR: src per slot
__device__ int    g_dsts[N_EDGES];               // CSR: dst per slot

__device__ __forceinline__ float lrelu(float v) { return v > 0.f ? v : NEG * v; }

// packed f32x2 helpers (sm_103a; ptxas never auto-fuses these)
__device__ __forceinline__ unsigned long long pack2(float lo, float hi) {
    unsigned long long r;
    asm("mov.b64 %0, {%1, %2};" : "=l"(r) : "f"(lo), "f"(hi));
    return r;
}
__device__ __forceinline__ void unpack2(unsigned long long v, float& lo, float& hi) {
    asm("mov.b64 {%0, %1}, %2;" : "=f"(lo), "=f"(hi) : "l"(v));
}
__device__ __forceinline__ void ffma2(unsigned long long& d,
                                      unsigned long long a, unsigned long long b) {
    asm("fma.rn.f32x2 %0, %1, %2, %3;" : "=l"(d) : "l"(a), "l"(b), "l"(d));
}

// ---------------------------------------------------------------------------
// K1: x_l = X@W_l + b_l ; x_r = X@W_r + b_r, fp16, HEAD-MAJOR layout.
// ---------------------------------------------------------------------------
__global__ __launch_bounds__(256) void proj_kernel(
    const float* __restrict__ X,
    const float* __restrict__ Wl, const float* __restrict__ bl,
    const float* __restrict__ Wr, const float* __restrict__ br)
{
    __shared__ float sx[128 * IN_DIM];
    const int c0 = threadIdx.x * 2;
    const int hh = c0 >> 7;          // head of both columns
    const int oc0 = c0 & 127;        // column within head
    unsigned long long wl[IN_DIM], wr[IN_DIM];
#pragma unroll
    for (int k = 0; k < IN_DIM; k++) {
        wl[k] = pack2(Wl[k * HC + c0], Wl[k * HC + c0 + 1]);
        wr[k] = pack2(Wr[k * HC + c0], Wr[k * HC + c0 + 1]);
    }
    const unsigned long long bl2 = pack2(bl[c0], bl[c0 + 1]);
    const unsigned long long br2 = pack2(br[c0], br[c0 + 1]);

    const int n0 = blockIdx.x * 128;
    const int nmax = min(128, N_NODES - n0);

    for (int i = threadIdx.x; i < nmax * IN_DIM; i += blockDim.x)
        sx[i] = X[(size_t)n0 * IN_DIM + i];
    __syncthreads();

    for (int n = 0; n < nmax; n++) {
        unsigned long long al = bl2, ar = br2;
#pragma unroll
        for (int k = 0; k < IN_DIM; k++) {
            const float xv = sx[n * IN_DIM + k];
            const unsigned long long x2 = pack2(xv, xv);
            ffma2(al, x2, wl[k]);
            ffma2(ar, x2, wr[k]);
        }
        float l0, l1, r0, r1;
        unpack2(al, l0, l1);
        unpack2(ar, r0, r1);
        // head-major half2 index
        const size_t o = (size_t)(hh * N_NODES + (n0 + n)) * 64 + (oc0 >> 1);
        ((__half2*)g_xl)[o] = __floats2half2_rn(l0, l1);
        ((__half2*)g_xr)[o] = __floats2half2_rn(r0, r1);
    }
}

// ---------------------------------------------------------------------------
// CSR build: histogram -> single-block scan -> fill
// ---------------------------------------------------------------------------
__global__ __launch_bounds__(256) void hist_kernel(const int* __restrict__ idx)
{
    const int e = blockIdx.x * blockDim.x + threadIdx.x;
    if (e < N_EDGES) atomicAdd(&g_counts[idx[N_EDGES + e]], 1);
}

__global__ __launch_bounds__(1024) void scan_kernel()
{
    __shared__ int sp[1024];
    const int t = threadIdx.x;
    const int CH = (N_NODES + 1023) / 1024;
    const int base = t * CH;
    const int lim = min(CH, N_NODES - base);

    int sum = 0;
    for (int i = 0; i < lim; i++) sum += g_counts[base + i];
    sp[t] = sum;
    __syncthreads();
    for (int off = 1; off < 1024; off <<= 1) {
        int v = (t >= off) ? sp[t - off] : 0;
        __syncthreads();
        sp[t] += v;
        __syncthreads();
    }
    int run = (t > 0) ? sp[t - 1] : 0;
    for (int i = 0; i < lim; i++) {
        g_row[base + i] = run;
        g_cursor[base + i] = run;
        run += g_counts[base + i];
    }
    if (t == 0) g_row[N_NODES] = N_EDGES;
}

__global__ __launch_bounds__(256) void fill_kernel(const int* __restrict__ idx)
{
    const int e = blockIdx.x * blockDim.x + threadIdx.x;
    if (e >= N_EDGES) return;
    const int dst = idx[N_EDGES + e];
    const int pos = atomicAdd(&g_cursor[dst], 1);
    g_srcs[pos] = idx[e];
    g_dsts[pos] = dst;
}

// ---------------------------------------------------------------------------
// K2: per-HEAD edge scores. One pass per head (sequential launches): the
// pass working set x_l_h + x_r_h = 51.2 MB is L2-resident, so the 256 MB of
// random row gathers per pass is served from L2 instead of DRAM.
// One warp per CSR slot; lane loads uint2 (4 halves) -> row = 32 lanes x 8B.
// No max-subtraction: scores are O(1), exp safe in fp32, softmax ratio exact.
// ---------------------------------------------------------------------------
__global__ __launch_bounds__(256) void score_head_kernel(
    const float* __restrict__ att, const int h)
{
    const int j = blockIdx.x * 8 + (threadIdx.x >> 5);
    if (j >= N_EDGES) return;
    const int lane = threadIdx.x & 31;
    const int src = g_srcs[j];
    const int dst = g_dsts[j];

    const uint2* __restrict__ xlh = ((const uint2*)g_xl) + (size_t)(h * N_NODES + src) * 32;
    const uint2* __restrict__ xrh = ((const uint2*)g_xr) + (size_t)(h * N_NODES + dst) * 32;

    const uint2 ap = xlh[lane];
    const uint2 bp = xrh[lane];
    const float2 a0 = __half22float2(*(const __half2*)&ap.x);
    const float2 a1 = __half22float2(*(const __half2*)&ap.y);
    const float2 b0 = __half22float2(*(const __half2*)&bp.x);
    const float2 b1 = __half22float2(*(const __half2*)&bp.y);

    const float4 w = __ldg(&((const float4*)att)[h * 32 + lane]);
    float s = lrelu(a0.x + b0.x) * w.x;
    s = fmaf(lrelu(a0.y + b0.y), w.y, s);
    s = fmaf(lrelu(a1.x + b1.x), w.z, s);
    s = fmaf(lrelu(a1.y + b1.y), w.w, s);
#pragma unroll
    for (int off = 16; off > 0; off >>= 1)
        s += __shfl_xor_sync(0xffffffffu, s, off);

    if (lane == 0)
        g_ex[(size_t)j * HEADS + h] = __expf(s);
}

// ---------------------------------------------------------------------------
// K3: X-space aggregation (linearity: out = (sum alpha X[src]) @ W_l + b_l).
// One warp per node; X gathers are L2-resident (6.4 MB). Writes normalized y
// and per-head gate. (unchanged from R9)
// ---------------------------------------------------------------------------
__global__ __launch_bounds__(256) void aggregate_kernel(const float* __restrict__ X)
{
    const int node = blockIdx.x * 8 + (threadIdx.x >> 5);
    if (node >= N_NODES) return;
    const int lane = threadIdx.x & 31;
    const int k = lane & 15;
    const int half = lane >> 4;

    const int eb = g_row[node];
    const int ee = g_row[node + 1];

    float yA = 0.f, yB = 0.f;             // heads: half and 2+half
    float4 den = make_float4(0.f, 0.f, 0.f, 0.f);

    for (int j = eb; j < ee; j++) {
        const int src = g_srcs[j];                         // lane-uniform
        const float4 ex = __ldg(&((const float4*)g_ex)[j]);
        const float xv = __ldg(&X[(size_t)src * IN_DIM + k]);
        const float wA = half ? ex.y : ex.x;
        const float wB = half ? ex.w : ex.z;
        yA = fmaf(wA, xv, yA);
        yB = fmaf(wB, xv, yB);
        den.x += ex.x; den.y += ex.y; den.z += ex.z; den.w += ex.w;
    }

    const float dA = half ? den.y : den.x;
    const float dB = half ? den.w : den.z;
    const float iA = (dA > 0.f) ? (1.0f / dA) : 0.f;
    const float iB = (dB > 0.f) ? (1.0f / dB) : 0.f;

    g_y[(size_t)node * 64 + lane]      = yA * iA;
    g_y[(size_t)node * 64 + 32 + lane] = yB * iB;
    if (lane < 4) {
        const float d = (lane == 0) ? den.x : (lane == 1) ? den.y
                      : (lane == 2) ? den.z : den.w;
        g_gate[node * HEADS + lane] = (d > 0.f) ? 1.f : 0.f;
    }
}

// ---------------------------------------------------------------------------
// K4: out[node] = y_norm[node] @ W_l + gate*b_l + bias. (unchanged from R9)
// ---------------------------------------------------------------------------
__global__ __launch_bounds__(256) void outproj_kernel(
    const float* __restrict__ Wl, const float* __restrict__ bl,
    const float* __restrict__ bias, float* __restrict__ out)
{
    __shared__ float sy[128 * 64];   // 32 KB
    __shared__ float sg[128 * HEADS];
    const int c0 = threadIdx.x * 2;
    const int hh = c0 >> 7;

    unsigned long long w[IN_DIM];
#pragma unroll
    for (int k = 0; k < IN_DIM; k++)
        w[k] = pack2(Wl[k * HC + c0], Wl[k * HC + c0 + 1]);
    const float bl0 = bl[c0], bl1 = bl[c0 + 1];
    const float bs0 = bias[c0], bs1 = bias[c0 + 1];

    const int n0 = blockIdx.x * 128;
    const int nmax = min(128, N_NODES - n0);

    for (int i = threadIdx.x; i < nmax * 64; i += blockDim.x)
        sy[i] = g_y[(size_t)n0 * 64 + i];
    for (int i = threadIdx.x; i < nmax * HEADS; i += blockDim.x)
        sg[i] = g_gate[n0 * HEADS + i];
    __syncthreads();

    for (int n = 0; n < nmax; n++) {
        const float gate = sg[n * HEADS + hh];
        unsigned long long acc = pack2(fmaf(gate, bl0, bs0), fmaf(gate, bl1, bs1));
        const float* yrow = sy + n * 64 + hh * 16;
#pragma unroll
        for (int k = 0; k < IN_DIM; k++) {
            const float yv = yrow[k];
            ffma2(acc, pack2(yv, yv), w[k]);
        }
        float o0, o1;
        unpack2(acc, o0, o1);
        ((float2*)out)[((size_t)(n0 + n) * HC + c0) >> 1] = make_float2(o0, o1);
    }
}

// ---------------------------------------------------------------------------
extern "C" void kernel_launch(void* const* d_in, const int* in_sizes, int n_in,
                              void* d_out, int out_size)
{
    const float* X    = (const float*)d_in[0];  // [N, 16]
    const int*   idx  = (const int*)  d_in[1];  // [2, E]
    const float* Wl   = (const float*)d_in[2];  // [16, 512]
    const float* bl   = (const float*)d_in[3];  // [512]
    const float* Wr   = (const float*)d_in[4];  // [16, 512]
    const float* br   = (const float*)d_in[5];  // [512]
    const float* att  = (const float*)d_in[6];  // [4, 128]
    const float* bias = (const float*)d_in[7];  // [512]
    float* out = (float*)d_out;                 // [N, 512]

    void* counts_ptr = nullptr;
    cudaGetSymbolAddress(&counts_ptr, g_counts);
    cudaMemsetAsync(counts_ptr, 0, N_NODES * sizeof(int), 0);

    proj_kernel<<<(N_NODES + 127) / 128, 256>>>(X, Wl, bl, Wr, br);
    hist_kernel<<<(N_EDGES + 255) / 256, 256>>>(idx);
    scan_kernel<<<1, 1024>>>();
    fill_kernel<<<(N_EDGES + 255) / 256, 256>>>(idx);
    for (int h = 0; h < HEADS; h++)
        score_head_kernel<<<(N_EDGES + 7) / 8, 256>>>(att, h);
    aggregate_kernel<<<(N_NODES + 7) / 8, 256>>>(X);
    outproj_kernel<<<(N_NODES + 127) / 128, 256>>>(Wl, bl, bias, out);
}

// round 13
// speedup vs baseline: 1.5511x; 1.5511x over previous
#include <cuda_runtime.h>
#include <cuda_fp16.h>
#include <cstdint>

#define N_NODES 100000
#define N_EDGES 500000
#define IN_DIM 16
#define HEADS 4
#define OUT_DIM 128
#define HC 512           // HEADS*OUT_DIM
#define NEG 0.2f

#define TILE_M 128       // edges per block-tile (8 warps x 16)
#define TS_THREADS 256
#define TS_GRID 296      // persistent; 2 blocks/SM
#define N_TILES ((N_EDGES + TILE_M - 1) / TILE_M)
#define BK 56            // padded K stride (halves) for conflict-free LDS
#define SMEM_TS (2048 + 512 * BK * 2)   // att[512] f32 + B[512][56] f16

// Scratch (device globals: allocation-free per harness rules)
__device__ __half g_xf16[(size_t)N_NODES * IN_DIM];   // fp16 X, 3.2 MB (L2-resident)
__device__ float  g_ex[(size_t)N_EDGES * HEADS];      // 8 MB, [slot][h]
__device__ float  g_y[(size_t)N_NODES * 64];          // normalized alpha-weighted X sums
__device__ float  g_gate[(size_t)N_NODES * HEADS];
__device__ int    g_counts[N_NODES];
__device__ int    g_row[N_NODES + 1];
__device__ int    g_cursor[N_NODES];
__device__ int    g_srcs[N_EDGES];                    // CSR: src per slot
__device__ int    g_dsts[N_EDGES];                    // CSR: dst per slot

__device__ __forceinline__ float lrelu(float v) { return fmaxf(v, NEG * v); }

// packed f32x2 helpers
__device__ __forceinline__ unsigned long long pack2(float lo, float hi) {
    unsigned long long r;
    asm("mov.b64 %0, {%1, %2};" : "=l"(r) : "f"(lo), "f"(hi));
    return r;
}
__device__ __forceinline__ void unpack2(unsigned long long v, float& lo, float& hi) {
    asm("mov.b64 {%0, %1}, %2;" : "=f"(lo), "=f"(hi) : "l"(v));
}
__device__ __forceinline__ void ffma2(unsigned long long& d,
                                      unsigned long long a, unsigned long long b) {
    asm("fma.rn.f32x2 %0, %1, %2, %3;" : "=l"(d) : "l"(a), "l"(b), "l"(d));
}

// HMMA m16n8k16 row.col f32 = f16*f16 + f32 (sm_80+, legal on compute_103)
__device__ __forceinline__ void mma16816(float* c, const uint32_t* a,
                                         uint32_t b0, uint32_t b1) {
    asm volatile(
        "mma.sync.aligned.m16n8k16.row.col.f32.f16.f16.f32 "
        "{%0,%1,%2,%3}, {%4,%5,%6,%7}, {%8,%9}, {%0,%1,%2,%3};"
        : "+f"(c[0]), "+f"(c[1]), "+f"(c[2]), "+f"(c[3])
        : "r"(a[0]), "r"(a[1]), "r"(a[2]), "r"(a[3]), "r"(b0), "r"(b1));
}

// ---------------------------------------------------------------------------
// K0: X -> fp16 copy
// ---------------------------------------------------------------------------
__global__ __launch_bounds__(256) void xcvt_kernel(const float* __restrict__ X)
{
    const int i = blockIdx.x * blockDim.x + threadIdx.x;
    if (i < N_NODES * IN_DIM) g_xf16[i] = __float2half_rn(X[i]);
}

// ---------------------------------------------------------------------------
// CSR build: histogram -> single-block scan -> fill
// ---------------------------------------------------------------------------
__global__ __launch_bounds__(256) void hist_kernel(const int* __restrict__ idx)
{
    const int e = blockIdx.x * blockDim.x + threadIdx.x;
    if (e < N_EDGES) atomicAdd(&g_counts[idx[N_EDGES + e]], 1);
}

__global__ __launch_bounds__(1024) void scan_kernel()
{
    __shared__ int sp[1024];
    const int t = threadIdx.x;
    const int CH = (N_NODES + 1023) / 1024;
    const int base = t * CH;
    const int lim = min(CH, N_NODES - base);

    int sum = 0;
    for (int i = 0; i < lim; i++) sum += g_counts[base + i];
    sp[t] = sum;
    __syncthreads();
    for (int off = 1; off < 1024; off <<= 1) {
        int v = (t >= off) ? sp[t - off] : 0;
        __syncthreads();
        sp[t] += v;
        __syncthreads();
    }
    int run = (t > 0) ? sp[t - 1] : 0;
    for (int i = 0; i < lim; i++) {
        g_row[base + i] = run;
        g_cursor[base + i] = run;
        run += g_counts[base + i];
    }
    if (t == 0) g_row[N_NODES] = N_EDGES;
}

__global__ __launch_bounds__(256) void fill_kernel(const int* __restrict__ idx)
{
    const int e = blockIdx.x * blockDim.x + threadIdx.x;
    if (e >= N_EDGES) return;
    const int dst = idx[N_EDGES + e];
    const int pos = atomicAdd(&g_cursor[dst], 1);
    g_srcs[pos] = idx[e];
    g_dsts[pos] = dst;
}

// ---------------------------------------------------------------------------
// K2: tensor-core (HMMA) edge scores. Persistent blocks of 8 warps.
//   Per-warp tile: A[16 edges, K=48] = [X(src)|X(dst)|1], fragments gathered
//   directly from L2-resident g_xf16. B[K=48, N=512] = [Wl;Wr;bl+br] staged
//   once per block in smem (rows padded to 56 halves -> conflict-free).
//   q = A@B (fp32) per edge; epilogue folds lrelu*att into per-head accs,
//   quad-reduce via 2 shuffles, expf, float4 store to g_ex[slot].
// No max-subtraction: scores are O(1), exp safe in fp32, softmax ratio exact.
// ---------------------------------------------------------------------------
__global__ __launch_bounds__(TS_THREADS, 2) void tensor_score_kernel(
    const float* __restrict__ Wl, const float* __restrict__ bl,
    const float* __restrict__ Wr, const float* __restrict__ br,
    const float* __restrict__ att)
{
    extern __shared__ char dsm[];
    float* satt = (float*)dsm;                 // 512 f32
    __half* sB = (__half*)(dsm + 2048);        // [512][BK]

    const int tid = threadIdx.x;

    for (int i = tid; i < HC; i += TS_THREADS) satt[i] = att[i];
    for (int i = tid; i < 512 * BK; i += TS_THREADS) {
        const int n = i / BK, k = i % BK;
        float v = 0.f;
        if (k < 16)       v = Wl[k * HC + n];
        else if (k < 32)  v = Wr[(k - 16) * HC + n];
        else if (k == 32) v = bl[n] + br[n];
        sB[n * BK + k] = __float2half_rn(v);
    }
    __syncthreads();

    const int w = tid >> 5;
    const int lane = tid & 31;
    const int g = lane >> 2;   // row group (0..7)
    const int t4 = lane & 3;   // thread-in-quad

    // constant kstep2 A fragment: k=32 -> 1.0 (only t4==0 low half)
    uint32_t aC[4];
    aC[0] = (t4 == 0) ? 0x00003C00u : 0u;
    aC[1] = aC[0];
    aC[2] = 0u;
    aC[3] = 0u;

    for (int tile = blockIdx.x; tile < N_TILES; tile += gridDim.x) {
        const int e_lo = tile * TILE_M + w * 16 + g;
        const int e_hi = e_lo + 8;
        const int je_lo = min(e_lo, N_EDGES - 1);
        const int je_hi = min(e_hi, N_EDGES - 1);
        const int s_lo = __ldg(&g_srcs[je_lo]);
        const int s_hi = __ldg(&g_srcs[je_hi]);
        const int d_lo = __ldg(&g_dsts[je_lo]);
        const int d_hi = __ldg(&g_dsts[je_hi]);

        // A fragments: kstep0 = X[src], kstep1 = X[dst]
        const uint32_t* xs_lo = (const uint32_t*)(g_xf16 + (size_t)s_lo * IN_DIM);
        const uint32_t* xs_hi = (const uint32_t*)(g_xf16 + (size_t)s_hi * IN_DIM);
        const uint32_t* xd_lo = (const uint32_t*)(g_xf16 + (size_t)d_lo * IN_DIM);
        const uint32_t* xd_hi = (const uint32_t*)(g_xf16 + (size_t)d_hi * IN_DIM);
        uint32_t a0[4], a1[4];
        a0[0] = __ldg(&xs_lo[t4]);     a0[1] = __ldg(&xs_hi[t4]);
        a0[2] = __ldg(&xs_lo[t4 + 4]); a0[3] = __ldg(&xs_hi[t4 + 4]);
        a1[0] = __ldg(&xd_lo[t4]);     a1[1] = __ldg(&xd_hi[t4]);
        a1[2] = __ldg(&xd_lo[t4 + 4]); a1[3] = __ldg(&xd_hi[t4 + 4]);

        float acc[2][HEADS];
#pragma unroll
        for (int r = 0; r < 2; r++)
#pragma unroll
            for (int h = 0; h < HEADS; h++) acc[r][h] = 0.f;

#pragma unroll 4
        for (int nt = 0; nt < 64; nt++) {
            const int h = nt >> 4;
            const __half* bp = sB + (nt * 8 + g) * BK + t4 * 2;
            const uint32_t b00 = *(const uint32_t*)(bp);
            const uint32_t b01 = *(const uint32_t*)(bp + 8);
            const uint32_t b10 = *(const uint32_t*)(bp + 16);
            const uint32_t b11 = *(const uint32_t*)(bp + 24);
            const uint32_t b20 = *(const uint32_t*)(bp + 32);
            const uint32_t b21 = *(const uint32_t*)(bp + 40);

            float c[4] = {0.f, 0.f, 0.f, 0.f};
            mma16816(c, a0, b00, b01);
            mma16816(c, a1, b10, b11);
            mma16816(c, aC, b20, b21);

            const float2 aw = *(const float2*)(satt + nt * 8 + t4 * 2);
            acc[0][h] = fmaf(lrelu(c[0]), aw.x, fmaf(lrelu(c[1]), aw.y, acc[0][h]));
            acc[1][h] = fmaf(lrelu(c[2]), aw.x, fmaf(lrelu(c[3]), aw.y, acc[1][h]));
        }

        // quad reduce: lanes xor 1, 2 within the 4-thread column group
#pragma unroll
        for (int r = 0; r < 2; r++)
#pragma unroll
            for (int h = 0; h < HEADS; h++) {
                float v = acc[r][h];
                v += __shfl_xor_sync(0xffffffffu, v, 1);
                v += __shfl_xor_sync(0xffffffffu, v, 2);
                acc[r][h] = v;
            }

        if (t4 == 0) {
            if (e_lo < N_EDGES)
                ((float4*)g_ex)[e_lo] = make_float4(
                    __expf(acc[0][0]), __expf(acc[0][1]),
                    __expf(acc[0][2]), __expf(acc[0][3]));
            if (e_hi < N_EDGES)
                ((float4*)g_ex)[e_hi] = make_float4(
                    __expf(acc[1][0]), __expf(acc[1][1]),
                    __expf(acc[1][2]), __expf(acc[1][3]));
        }
    }
}

// ---------------------------------------------------------------------------
// K3: X-space aggregation (linearity: out = (sum alpha X[src]) @ W_l + b_l).
// One warp per node; X gathers are L2-resident. (unchanged from R9)
// ---------------------------------------------------------------------------
__global__ __launch_bounds__(256) void aggregate_kernel(const float* __restrict__ X)
{
    const int node = blockIdx.x * 8 + (threadIdx.x >> 5);
    if (node >= N_NODES) return;
    const int lane = threadIdx.x & 31;
    const int k = lane & 15;
    const int half = lane >> 4;

    const int eb = g_row[node];
    const int ee = g_row[node + 1];

    float yA = 0.f, yB = 0.f;             // heads: half and 2+half
    float4 den = make_float4(0.f, 0.f, 0.f, 0.f);

    for (int j = eb; j < ee; j++) {
        const int src = g_srcs[j];                         // lane-uniform
        const float4 ex = __ldg(&((const float4*)g_ex)[j]);
        const float xv = __ldg(&X[(size_t)src * IN_DIM + k]);
        const float wA = half ? ex.y : ex.x;
        const float wB = half ? ex.w : ex.z;
        yA = fmaf(wA, xv, yA);
        yB = fmaf(wB, xv, yB);
        den.x += ex.x; den.y += ex.y; den.z += ex.z; den.w += ex.w;
    }

    const float dA = half ? den.y : den.x;
    const float dB = half ? den.w : den.z;
    const float iA = (dA > 0.f) ? (1.0f / dA) : 0.f;
    const float iB = (dB > 0.f) ? (1.0f / dB) : 0.f;

    g_y[(size_t)node * 64 + lane]      = yA * iA;
    g_y[(size_t)node * 64 + 32 + lane] = yB * iB;
    if (lane < 4) {
        const float d = (lane == 0) ? den.x : (lane == 1) ? den.y
                      : (lane == 2) ? den.z : den.w;
        g_gate[node * HEADS + lane] = (d > 0.f) ? 1.f : 0.f;
    }
}

// ---------------------------------------------------------------------------
// K4: out[node] = y_norm[node] @ W_l + gate*b_l + bias. (unchanged from R9)
// ---------------------------------------------------------------------------
__global__ __launch_bounds__(256) void outproj_kernel(
    const float* __restrict__ Wl, const float* __restrict__ bl,
    const float* __restrict__ bias, float* __restrict__ out)
{
    __shared__ float sy[128 * 64];   // 32 KB
    __shared__ float sg[128 * HEADS];
    const int c0 = threadIdx.x * 2;
    const int hh = c0 >> 7;

    unsigned long long w[IN_DIM];
#pragma unroll
    for (int k = 0; k < IN_DIM; k++)
        w[k] = pack2(Wl[k * HC + c0], Wl[k * HC + c0 + 1]);
    const float bl0 = bl[c0], bl1 = bl[c0 + 1];
    const float bs0 = bias[c0], bs1 = bias[c0 + 1];

    const int n0 = blockIdx.x * 128;
    const int nmax = min(128, N_NODES - n0);

    for (int i = threadIdx.x; i < nmax * 64; i += blockDim.x)
        sy[i] = g_y[(size_t)n0 * 64 + i];
    for (int i = threadIdx.x; i < nmax * HEADS; i += blockDim.x)
        sg[i] = g_gate[n0 * HEADS + i];
    __syncthreads();

    for (int n = 0; n < nmax; n++) {
        const float gate = sg[n * HEADS + hh];
        unsigned long long acc = pack2(fmaf(gate, bl0, bs0), fmaf(gate, bl1, bs1));
        const float* yrow = sy + n * 64 + hh * 16;
#pragma unroll
        for (int k = 0; k < IN_DIM; k++) {
            const float yv = yrow[k];
            ffma2(acc, pack2(yv, yv), w[k]);
        }
        float o0, o1;
        unpack2(acc, o0, o1);
        ((float2*)out)[((size_t)(n0 + n) * HC + c0) >> 1] = make_float2(o0, o1);
    }
}

// ---------------------------------------------------------------------------
extern "C" void kernel_launch(void* const* d_in, const int* in_sizes, int n_in,
                              void* d_out, int out_size)
{
    const float* X    = (const float*)d_in[0];  // [N, 16]
    const int*   idx  = (const int*)  d_in[1];  // [2, E]
    const float* Wl   = (const float*)d_in[2];  // [16, 512]
    const float* bl   = (const float*)d_in[3];  // [512]
    const float* Wr   = (const float*)d_in[4];  // [16, 512]
    const float* br   = (const float*)d_in[5];  // [512]
    const float* att  = (const float*)d_in[6];  // [4, 128]
    const float* bias = (const float*)d_in[7];  // [512]
    float* out = (float*)d_out;                 // [N, 512]

    void* counts_ptr = nullptr;
    cudaGetSymbolAddress(&counts_ptr, g_counts);
    cudaMemsetAsync(counts_ptr, 0, N_NODES * sizeof(int), 0);

    cudaFuncSetAttribute(tensor_score_kernel,
                         cudaFuncAttributeMaxDynamicSharedMemorySize, SMEM_TS);

    xcvt_kernel<<<(N_NODES * IN_DIM + 255) / 256, 256>>>(X);
    hist_kernel<<<(N_EDGES + 255) / 256, 256>>>(idx);
    scan_kernel<<<1, 1024>>>();
    fill_kernel<<<(N_EDGES + 255) / 256, 256>>>(idx);
    tensor_score_kernel<<<TS_GRID, TS_THREADS, SMEM_TS>>>(Wl, bl, Wr, br, att);
    aggregate_kernel<<<(N_NODES + 7) / 8, 256>>>(X);
    outproj_kernel<<<(N_NODES + 127) / 128, 256>>>(Wl, bl, bias, out);
}

// round 14
// speedup vs baseline: 2.5316x; 1.6321x over previous
#include <cuda_runtime.h>
#include <cuda_fp16.h>
#include <cstdint>

#define N_NODES 100000
#define N_EDGES 500000
#define IN_DIM 16
#define HEADS 4
#define OUT_DIM 128
#define HC 512           // HEADS*OUT_DIM
#define NEG 0.2f

#define TILE_M 128       // edges per block-tile (8 warps x 16)
#define TS_THREADS 256
#define TS_GRID 296      // persistent; 2 blocks/SM
#define N_TILES ((N_EDGES + TILE_M - 1) / TILE_M)
#define BK 56            // padded K stride (halves) for conflict-free LDS
#define SMEM_TS (2048 + 512 * BK * 2)   // att[512] f32 + B[512][56] f16

#define SCAN_CHUNK 256
#define N_CHUNKS ((N_NODES + SCAN_CHUNK - 1) / SCAN_CHUNK)   // 391

// Scratch (device globals: allocation-free per harness rules)
__device__ __half g_xf16[(size_t)N_NODES * IN_DIM];   // fp16 X, 3.2 MB (L2-resident)
__device__ float  g_ex[(size_t)N_EDGES * HEADS];      // 8 MB, [slot][h]
__device__ float  g_y[(size_t)N_NODES * 64];          // normalized alpha-weighted X sums
__device__ float  g_gate[(size_t)N_NODES * HEADS];
__device__ int    g_counts[N_NODES];
__device__ int    g_row[N_NODES + 1];
__device__ int    g_cursor[N_NODES];
__device__ int    g_chunksum[N_CHUNKS];               // inclusive chunk sums
__device__ int    g_srcs[N_EDGES];                    // CSR: src per slot
__device__ int    g_dsts[N_EDGES];                    // CSR: dst per slot

__device__ __forceinline__ float lrelu(float v) { return fmaxf(v, NEG * v); }

// packed f32x2 helpers
__device__ __forceinline__ unsigned long long pack2(float lo, float hi) {
    unsigned long long r;
    asm("mov.b64 %0, {%1, %2};" : "=l"(r) : "f"(lo), "f"(hi));
    return r;
}
__device__ __forceinline__ void unpack2(unsigned long long v, float& lo, float& hi) {
    asm("mov.b64 {%0, %1}, %2;" : "=f"(lo), "=f"(hi) : "l"(v));
}
__device__ __forceinline__ void ffma2(unsigned long long& d,
                                      unsigned long long a, unsigned long long b) {
    asm("fma.rn.f32x2 %0, %1, %2, %3;" : "=l"(d) : "l"(a), "l"(b), "l"(d));
}

// HMMA m16n8k16 row.col f32 = f16*f16 + f32 (sm_80+, legal on compute_103)
__device__ __forceinline__ void mma16816(float* c, const uint32_t* a,
                                         uint32_t b0, uint32_t b1) {
    asm volatile(
        "mma.sync.aligned.m16n8k16.row.col.f32.f16.f16.f32 "
        "{%0,%1,%2,%3}, {%4,%5,%6,%7}, {%8,%9}, {%0,%1,%2,%3};"
        : "+f"(c[0]), "+f"(c[1]), "+f"(c[2]), "+f"(c[3])
        : "r"(a[0]), "r"(a[1]), "r"(a[2]), "r"(a[3]), "r"(b0), "r"(b1));
}

// ---------------------------------------------------------------------------
// K0: X -> fp16 copy
// ---------------------------------------------------------------------------
__global__ __launch_bounds__(256) void xcvt_kernel(const float* __restrict__ X)
{
    const int i = blockIdx.x * blockDim.x + threadIdx.x;
    if (i < N_NODES * IN_DIM) g_xf16[i] = __float2half_rn(X[i]);
}

// ---------------------------------------------------------------------------
// CSR build: histogram -> PARALLEL 3-stage scan -> fill
// ---------------------------------------------------------------------------
__global__ __launch_bounds__(256) void hist_kernel(const int* __restrict__ idx)
{
    const int e = blockIdx.x * blockDim.x + threadIdx.x;
    if (e < N_EDGES) atomicAdd(&g_counts[idx[N_EDGES + e]], 1);
}

// stage A: per-chunk sums (coalesced, parallel)
__global__ __launch_bounds__(SCAN_CHUNK) void scanA_kernel()
{
    __shared__ int sp[SCAN_CHUNK];
    const int gid = blockIdx.x * SCAN_CHUNK + threadIdx.x;
    sp[threadIdx.x] = (gid < N_NODES) ? g_counts[gid] : 0;
    __syncthreads();
    for (int off = SCAN_CHUNK / 2; off > 0; off >>= 1) {
        if (threadIdx.x < off) sp[threadIdx.x] += sp[threadIdx.x + off];
        __syncthreads();
    }
    if (threadIdx.x == 0) g_chunksum[blockIdx.x] = sp[0];
}

// stage B: single small block scans the 391 chunk sums (inclusive)
__global__ __launch_bounds__(512) void scanB_kernel()
{
    __shared__ int sp[512];
    const int t = threadIdx.x;
    sp[t] = (t < N_CHUNKS) ? g_chunksum[t] : 0;
    __syncthreads();
    for (int off = 1; off < 512; off <<= 1) {
        int v = (t >= off) ? sp[t - off] : 0;
        __syncthreads();
        sp[t] += v;
        __syncthreads();
    }
    if (t < N_CHUNKS) g_chunksum[t] = sp[t];   // inclusive
}

// stage C: in-chunk exclusive scan + chunk base -> row/cursor (coalesced)
__global__ __launch_bounds__(SCAN_CHUNK) void scanC_kernel()
{
    __shared__ int sp[SCAN_CHUNK];
    const int t = threadIdx.x;
    const int gid = blockIdx.x * SCAN_CHUNK + t;
    const int c = (gid < N_NODES) ? g_counts[gid] : 0;
    sp[t] = c;
    __syncthreads();
    for (int off = 1; off < SCAN_CHUNK; off <<= 1) {
        int v = (t >= off) ? sp[t - off] : 0;
        __syncthreads();
        sp[t] += v;
        __syncthreads();
    }
    const int base = (blockIdx.x > 0) ? g_chunksum[blockIdx.x - 1] : 0;
    const int val = base + sp[t] - c;   // exclusive prefix
    if (gid < N_NODES) {
        g_row[gid] = val;
        g_cursor[gid] = val;
    }
    if (gid == N_NODES) g_row[N_NODES] = N_EDGES;
    if (blockIdx.x == N_CHUNKS - 1 && t == SCAN_CHUNK - 1)
        g_row[N_NODES] = N_EDGES;   // ensure set even if gid==N never hit
}

__global__ __launch_bounds__(256) void fill_kernel(const int* __restrict__ idx)
{
    const int e = blockIdx.x * blockDim.x + threadIdx.x;
    if (e >= N_EDGES) return;
    const int dst = idx[N_EDGES + e];
    const int pos = atomicAdd(&g_cursor[dst], 1);
    g_srcs[pos] = idx[e];
    g_dsts[pos] = dst;
}

// ---------------------------------------------------------------------------
// K2: tensor-core (HMMA) edge scores. (unchanged from the 399us version)
// ---------------------------------------------------------------------------
__global__ __launch_bounds__(TS_THREADS, 2) void tensor_score_kernel(
    const float* __restrict__ Wl, const float* __restrict__ bl,
    const float* __restrict__ Wr, const float* __restrict__ br,
    const float* __restrict__ att)
{
    extern __shared__ char dsm[];
    float* satt = (float*)dsm;                 // 512 f32
    __half* sB = (__half*)(dsm + 2048);        // [512][BK]

    const int tid = threadIdx.x;

    for (int i = tid; i < HC; i += TS_THREADS) satt[i] = att[i];
    for (int i = tid; i < 512 * BK; i += TS_THREADS) {
        const int n = i / BK, k = i % BK;
        float v = 0.f;
        if (k < 16)       v = Wl[k * HC + n];
        else if (k < 32)  v = Wr[(k - 16) * HC + n];
        else if (k == 32) v = bl[n] + br[n];
        sB[n * BK + k] = __float2half_rn(v);
    }
    __syncthreads();

    const int w = tid >> 5;
    const int lane = tid & 31;
    const int g = lane >> 2;   // row group (0..7)
    const int t4 = lane & 3;   // thread-in-quad

    uint32_t aC[4];
    aC[0] = (t4 == 0) ? 0x00003C00u : 0u;
    aC[1] = aC[0];
    aC[2] = 0u;
    aC[3] = 0u;

    for (int tile = blockIdx.x; tile < N_TILES; tile += gridDim.x) {
        const int e_lo = tile * TILE_M + w * 16 + g;
        const int e_hi = e_lo + 8;
        const int je_lo = min(e_lo, N_EDGES - 1);
        const int je_hi = min(e_hi, N_EDGES - 1);
        const int s_lo = __ldg(&g_srcs[je_lo]);
        const int s_hi = __ldg(&g_srcs[je_hi]);
        const int d_lo = __ldg(&g_dsts[je_lo]);
        const int d_hi = __ldg(&g_dsts[je_hi]);

        const uint32_t* xs_lo = (const uint32_t*)(g_xf16 + (size_t)s_lo * IN_DIM);
        const uint32_t* xs_hi = (const uint32_t*)(g_xf16 + (size_t)s_hi * IN_DIM);
        const uint32_t* xd_lo = (const uint32_t*)(g_xf16 + (size_t)d_lo * IN_DIM);
        const uint32_t* xd_hi = (const uint32_t*)(g_xf16 + (size_t)d_hi * IN_DIM);
        uint32_t a0[4], a1[4];
        a0[0] = __ldg(&xs_lo[t4]);     a0[1] = __ldg(&xs_hi[t4]);
        a0[2] = __ldg(&xs_lo[t4 + 4]); a0[3] = __ldg(&xs_hi[t4 + 4]);
        a1[0] = __ldg(&xd_lo[t4]);     a1[1] = __ldg(&xd_hi[t4]);
        a1[2] = __ldg(&xd_lo[t4 + 4]); a1[3] = __ldg(&xd_hi[t4 + 4]);

        float acc[2][HEADS];
#pragma unroll
        for (int r = 0; r < 2; r++)
#pragma unroll
            for (int h = 0; h < HEADS; h++) acc[r][h] = 0.f;

#pragma unroll 4
        for (int nt = 0; nt < 64; nt++) {
            const int h = nt >> 4;
            const __half* bp = sB + (nt * 8 + g) * BK + t4 * 2;
            const uint32_t b00 = *(const uint32_t*)(bp);
            const uint32_t b01 = *(const uint32_t*)(bp + 8);
            const uint32_t b10 = *(const uint32_t*)(bp + 16);
            const uint32_t b11 = *(const uint32_t*)(bp + 24);
            const uint32_t b20 = *(const uint32_t*)(bp + 32);
            const uint32_t b21 = *(const uint32_t*)(bp + 40);

            float c[4] = {0.f, 0.f, 0.f, 0.f};
            mma16816(c, a0, b00, b01);
            mma16816(c, a1, b10, b11);
            mma16816(c, aC, b20, b21);

            const float2 aw = *(const float2*)(satt + nt * 8 + t4 * 2);
            acc[0][h] = fmaf(lrelu(c[0]), aw.x, fmaf(lrelu(c[1]), aw.y, acc[0][h]));
            acc[1][h] = fmaf(lrelu(c[2]), aw.x, fmaf(lrelu(c[3]), aw.y, acc[1][h]));
        }

#pragma unroll
        for (int r = 0; r < 2; r++)
#pragma unroll
            for (int h = 0; h < HEADS; h++) {
                float v = acc[r][h];
                v += __shfl_xor_sync(0xffffffffu, v, 1);
                v += __shfl_xor_sync(0xffffffffu, v, 2);
                acc[r][h] = v;
            }

        if (t4 == 0) {
            if (e_lo < N_EDGES)
                ((float4*)g_ex)[e_lo] = make_float4(
                    __expf(acc[0][0]), __expf(acc[0][1]),
                    __expf(acc[0][2]), __expf(acc[0][3]));
            if (e_hi < N_EDGES)
                ((float4*)g_ex)[e_hi] = make_float4(
                    __expf(acc[1][0]), __expf(acc[1][1]),
                    __expf(acc[1][2]), __expf(acc[1][3]));
        }
    }
}

// ---------------------------------------------------------------------------
// K3: X-space aggregation. (unchanged from R9)
// ---------------------------------------------------------------------------
__global__ __launch_bounds__(256) void aggregate_kernel(const float* __restrict__ X)
{
    const int node = blockIdx.x * 8 + (threadIdx.x >> 5);
    if (node >= N_NODES) return;
    const int lane = threadIdx.x & 31;
    const int k = lane & 15;
    const int half = lane >> 4;

    const int eb = g_row[node];
    const int ee = g_row[node + 1];

    float yA = 0.f, yB = 0.f;             // heads: half and 2+half
    float4 den = make_float4(0.f, 0.f, 0.f, 0.f);

    for (int j = eb; j < ee; j++) {
        const int src = g_srcs[j];                         // lane-uniform
        const float4 ex = __ldg(&((const float4*)g_ex)[j]);
        const float xv = __ldg(&X[(size_t)src * IN_DIM + k]);
        const float wA = half ? ex.y : ex.x;
        const float wB = half ? ex.w : ex.z;
        yA = fmaf(wA, xv, yA);
        yB = fmaf(wB, xv, yB);
        den.x += ex.x; den.y += ex.y; den.z += ex.z; den.w += ex.w;
    }

    const float dA = half ? den.y : den.x;
    const float dB = half ? den.w : den.z;
    const float iA = (dA > 0.f) ? (1.0f / dA) : 0.f;
    const float iB = (dB > 0.f) ? (1.0f / dB) : 0.f;

    g_y[(size_t)node * 64 + lane]      = yA * iA;
    g_y[(size_t)node * 64 + 32 + lane] = yB * iB;
    if (lane < 4) {
        const float d = (lane == 0) ? den.x : (lane == 1) ? den.y
                      : (lane == 2) ? den.z : den.w;
        g_gate[node * HEADS + lane] = (d > 0.f) ? 1.f : 0.f;
    }
}

// ---------------------------------------------------------------------------
// K4: out[node] = y_norm[node] @ W_l + gate*b_l + bias. (unchanged from R9)
// ---------------------------------------------------------------------------
__global__ __launch_bounds__(256) void outproj_kernel(
    const float* __restrict__ Wl, const float* __restrict__ bl,
    const float* __restrict__ bias, float* __restrict__ out)
{
    __shared__ float sy[128 * 64];   // 32 KB
    __shared__ float sg[128 * HEADS];
    const int c0 = threadIdx.x * 2;
    const int hh = c0 >> 7;

    unsigned long long w[IN_DIM];
#pragma unroll
    for (int k = 0; k < IN_DIM; k++)
        w[k] = pack2(Wl[k * HC + c0], Wl[k * HC + c0 + 1]);
    const float bl0 = bl[c0], bl1 = bl[c0 + 1];
    const float bs0 = bias[c0], bs1 = bias[c0 + 1];

    const int n0 = blockIdx.x * 128;
    const int nmax = min(128, N_NODES - n0);

    for (int i = threadIdx.x; i < nmax * 64; i += blockDim.x)
        sy[i] = g_y[(size_t)n0 * 64 + i];
    for (int i = threadIdx.x; i < nmax * HEADS; i += blockDim.x)
        sg[i] = g_gate[n0 * HEADS + i];
    __syncthreads();

    for (int n = 0; n < nmax; n++) {
        const float gate = sg[n * HEADS + hh];
        unsigned long long acc = pack2(fmaf(gate, bl0, bs0), fmaf(gate, bl1, bs1));
        const float* yrow = sy + n * 64 + hh * 16;
#pragma unroll
        for (int k = 0; k < IN_DIM; k++) {
            const float yv = yrow[k];
            ffma2(acc, pack2(yv, yv), w[k]);
        }
        float o0, o1;
        unpack2(acc, o0, o1);
        ((float2*)out)[((size_t)(n0 + n) * HC + c0) >> 1] = make_float2(o0, o1);
    }
}

// ---------------------------------------------------------------------------
extern "C" void kernel_launch(void* const* d_in, const int* in_sizes, int n_in,
                              void* d_out, int out_size)
{
    const float* X    = (const float*)d_in[0];  // [N, 16]
    const int*   idx  = (const int*)  d_in[1];  // [2, E]
    const float* Wl   = (const float*)d_in[2];  // [16, 512]
    const float* bl   = (const float*)d_in[3];  // [512]
    const float* Wr   = (const float*)d_in[4];  // [16, 512]
    const float* br   = (const float*)d_in[5];  // [512]
    const float* att  = (const float*)d_in[6];  // [4, 128]
    const float* bias = (const float*)d_in[7];  // [512]
    float* out = (float*)d_out;                 // [N, 512]

    void* counts_ptr = nullptr;
    cudaGetSymbolAddress(&counts_ptr, g_counts);
    cudaMemsetAsync(counts_ptr, 0, N_NODES * sizeof(int), 0);

    cudaFuncSetAttribute(tensor_score_kernel,
                         cudaFuncAttributeMaxDynamicSharedMemorySize, SMEM_TS);

    xcvt_kernel<<<(N_NODES * IN_DIM + 255) / 256, 256>>>(X);
    hist_kernel<<<(N_EDGES + 255) / 256, 256>>>(idx);
    scanA_kernel<<<N_CHUNKS, SCAN_CHUNK>>>();
    scanB_kernel<<<1, 512>>>();
    scanC_kernel<<<N_CHUNKS, SCAN_CHUNK>>>();
    fill_kernel<<<(N_EDGES + 255) / 256, 256>>>(idx);
    tensor_score_kernel<<<TS_GRID, TS_THREADS, SMEM_TS>>>(Wl, bl, Wr, br, att);
    aggregate_kernel<<<(N_NODES + 7) / 8, 256>>>(X);
    outproj_kernel<<<(N_NODES + 127) / 128, 256>>>(Wl, bl, bias, out);
}

// round 15
// speedup vs baseline: 2.7220x; 1.0752x over previous
#include <cuda_runtime.h>
#include <cuda_fp16.h>
#include <cstdint>

#define N_NODES 100000
#define N_EDGES 500000
#define IN_DIM 16
#define HEADS 4
#define OUT_DIM 128
#define HC 512           // HEADS*OUT_DIM
#define NEG 0.2f

#define TILE_M 256       // edges per block-tile (8 warps x 32)
#define TS_THREADS 256
#define TS_GRID 296      // persistent; 2 blocks/SM
#define N_TILES ((N_EDGES + TILE_M - 1) / TILE_M)
#define BK 56            // padded K stride (halves) for conflict-free LDS
#define SMEM_TS (2048 + 512 * BK * 2)   // att[512] f32 + B[512][56] f16

#define SCAN_CHUNK 256
#define N_CHUNKS ((N_NODES + SCAN_CHUNK - 1) / SCAN_CHUNK)   // 391

// Scratch (device globals: allocation-free per harness rules)
__device__ __half g_xf16[(size_t)N_NODES * IN_DIM];   // fp16 X, 3.2 MB (L2-resident)
__device__ float  g_ex[(size_t)N_EDGES * HEADS];      // 8 MB, [slot][h]
__device__ float  g_y[(size_t)N_NODES * 64];          // normalized alpha-weighted X sums
__device__ float  g_gate[(size_t)N_NODES * HEADS];
__device__ int    g_counts[N_NODES];
__device__ int    g_row[N_NODES + 1];
__device__ int    g_cursor[N_NODES];
__device__ int    g_chunksum[N_CHUNKS];               // inclusive chunk sums
__device__ int    g_srcs[N_EDGES];                    // CSR: src per slot
__device__ int    g_dsts[N_EDGES];                    // CSR: dst per slot

__device__ __forceinline__ float lrelu(float v) { return fmaxf(v, NEG * v); }

// packed f32x2 helpers
__device__ __forceinline__ unsigned long long pack2(float lo, float hi) {
    unsigned long long r;
    asm("mov.b64 %0, {%1, %2};" : "=l"(r) : "f"(lo), "f"(hi));
    return r;
}
__device__ __forceinline__ void unpack2(unsigned long long v, float& lo, float& hi) {
    asm("mov.b64 {%0, %1}, %2;" : "=f"(lo), "=f"(hi) : "l"(v));
}
__device__ __forceinline__ void ffma2(unsigned long long& d,
                                      unsigned long long a, unsigned long long b) {
    asm("fma.rn.f32x2 %0, %1, %2, %3;" : "=l"(d) : "l"(a), "l"(b), "l"(d));
}

// HMMA m16n8k16 row.col f32 = f16*f16 + f32 (sm_80+, legal on compute_103)
__device__ __forceinline__ void mma16816(float* c, const uint32_t* a,
                                         uint32_t b0, uint32_t b1) {
    asm volatile(
        "mma.sync.aligned.m16n8k16.row.col.f32.f16.f16.f32 "
        "{%0,%1,%2,%3}, {%4,%5,%6,%7}, {%8,%9}, {%0,%1,%2,%3};"
        : "+f"(c[0]), "+f"(c[1]), "+f"(c[2]), "+f"(c[3])
        : "r"(a[0]), "r"(a[1]), "r"(a[2]), "r"(a[3]), "r"(b0), "r"(b1));
}

// ---------------------------------------------------------------------------
// K0: X -> fp16 copy
// ---------------------------------------------------------------------------
__global__ __launch_bounds__(256) void xcvt_kernel(const float* __restrict__ X)
{
    const int i = blockIdx.x * blockDim.x + threadIdx.x;
    if (i < N_NODES * IN_DIM) g_xf16[i] = __float2half_rn(X[i]);
}

// ---------------------------------------------------------------------------
// CSR build: histogram -> PARALLEL 3-stage scan -> fill
// ---------------------------------------------------------------------------
__global__ __launch_bounds__(256) void hist_kernel(const int* __restrict__ idx)
{
    const int e = blockIdx.x * blockDim.x + threadIdx.x;
    if (e < N_EDGES) atomicAdd(&g_counts[idx[N_EDGES + e]], 1);
}

__global__ __launch_bounds__(SCAN_CHUNK) void scanA_kernel()
{
    __shared__ int sp[SCAN_CHUNK];
    const int gid = blockIdx.x * SCAN_CHUNK + threadIdx.x;
    sp[threadIdx.x] = (gid < N_NODES) ? g_counts[gid] : 0;
    __syncthreads();
    for (int off = SCAN_CHUNK / 2; off > 0; off >>= 1) {
        if (threadIdx.x < off) sp[threadIdx.x] += sp[threadIdx.x + off];
        __syncthreads();
    }
    if (threadIdx.x == 0) g_chunksum[blockIdx.x] = sp[0];
}

__global__ __launch_bounds__(512) void scanB_kernel()
{
    __shared__ int sp[512];
    const int t = threadIdx.x;
    sp[t] = (t < N_CHUNKS) ? g_chunksum[t] : 0;
    __syncthreads();
    for (int off = 1; off < 512; off <<= 1) {
        int v = (t >= off) ? sp[t - off] : 0;
        __syncthreads();
        sp[t] += v;
        __syncthreads();
    }
    if (t < N_CHUNKS) g_chunksum[t] = sp[t];   // inclusive
}

__global__ __launch_bounds__(SCAN_CHUNK) void scanC_kernel()
{
    __shared__ int sp[SCAN_CHUNK];
    const int t = threadIdx.x;
    const int gid = blockIdx.x * SCAN_CHUNK + t;
    const int c = (gid < N_NODES) ? g_counts[gid] : 0;
    sp[t] = c;
    __syncthreads();
    for (int off = 1; off < SCAN_CHUNK; off <<= 1) {
        int v = (t >= off) ? sp[t - off] : 0;
        __syncthreads();
        sp[t] += v;
        __syncthreads();
    }
    const int base = (blockIdx.x > 0) ? g_chunksum[blockIdx.x - 1] : 0;
    const int val = base + sp[t] - c;   // exclusive prefix
    if (gid < N_NODES) {
        g_row[gid] = val;
        g_cursor[gid] = val;
    }
    if (blockIdx.x == N_CHUNKS - 1 && t == SCAN_CHUNK - 1)
        g_row[N_NODES] = N_EDGES;
}

__global__ __launch_bounds__(256) void fill_kernel(const int* __restrict__ idx)
{
    const int e = blockIdx.x * blockDim.x + threadIdx.x;
    if (e >= N_EDGES) return;
    const int dst = idx[N_EDGES + e];
    const int pos = atomicAdd(&g_cursor[dst], 1);
    g_srcs[pos] = idx[e];
    g_dsts[pos] = dst;
}

// ---------------------------------------------------------------------------
// K2: tensor-core (HMMA) edge scores. 32 edges per warp (two 16-row A tiles
// sharing the same B smem loads -> B LDS + att loads amortized 2x vs R13).
// ---------------------------------------------------------------------------
__global__ __launch_bounds__(TS_THREADS, 2) void tensor_score_kernel(
    const float* __restrict__ Wl, const float* __restrict__ bl,
    const float* __restrict__ Wr, const float* __restrict__ br,
    const float* __restrict__ att)
{
    extern __shared__ char dsm[];
    float* satt = (float*)dsm;                 // 512 f32
    __half* sB = (__half*)(dsm + 2048);        // [512][BK]

    const int tid = threadIdx.x;

    for (int i = tid; i < HC; i += TS_THREADS) satt[i] = att[i];
    for (int i = tid; i < 512 * BK; i += TS_THREADS) {
        const int n = i / BK, k = i % BK;
        float v = 0.f;
        if (k < 16)       v = Wl[k * HC + n];
        else if (k < 32)  v = Wr[(k - 16) * HC + n];
        else if (k == 32) v = bl[n] + br[n];
        sB[n * BK + k] = __float2half_rn(v);
    }
    __syncthreads();

    const int w = tid >> 5;
    const int lane = tid & 31;
    const int g = lane >> 2;   // row group (0..7)
    const int t4 = lane & 3;   // thread-in-quad

    uint32_t aC[4];
    aC[0] = (t4 == 0) ? 0x00003C00u : 0u;
    aC[1] = aC[0];
    aC[2] = 0u;
    aC[3] = 0u;

    for (int tile = blockIdx.x; tile < N_TILES; tile += gridDim.x) {
        const int e0 = tile * TILE_M + w * 32 + g;   // pair0 row g
        const int e1 = e0 + 8;                        // pair0 row g+8
        const int e2 = e0 + 16;                       // pair1 row g
        const int e3 = e0 + 24;                       // pair1 row g+8

        int ec[4] = {e0, e1, e2, e3};
        uint32_t A[4][8];   // [pair*2 + half][frag]: a0/a1 per edge-pair
#pragma unroll
        for (int p = 0; p < 2; p++) {
            const int elo = min(ec[2 * p],     N_EDGES - 1);
            const int ehi = min(ec[2 * p + 1], N_EDGES - 1);
            const int s_lo = __ldg(&g_srcs[elo]);
            const int s_hi = __ldg(&g_srcs[ehi]);
            const int d_lo = __ldg(&g_dsts[elo]);
            const int d_hi = __ldg(&g_dsts[ehi]);
            const uint32_t* xs_lo = (const uint32_t*)(g_xf16 + (size_t)s_lo * IN_DIM);
            const uint32_t* xs_hi = (const uint32_t*)(g_xf16 + (size_t)s_hi * IN_DIM);
            const uint32_t* xd_lo = (const uint32_t*)(g_xf16 + (size_t)d_lo * IN_DIM);
            const uint32_t* xd_hi = (const uint32_t*)(g_xf16 + (size_t)d_hi * IN_DIM);
            // a0 (k-step 0: X[src])
            A[2 * p][0] = __ldg(&xs_lo[t4]);     A[2 * p][1] = __ldg(&xs_hi[t4]);
            A[2 * p][2] = __ldg(&xs_lo[t4 + 4]); A[2 * p][3] = __ldg(&xs_hi[t4 + 4]);
            // a1 (k-step 1: X[dst])
            A[2 * p + 1][0] = __ldg(&xd_lo[t4]);     A[2 * p + 1][1] = __ldg(&xd_hi[t4]);
            A[2 * p + 1][2] = __ldg(&xd_lo[t4 + 4]); A[2 * p + 1][3] = __ldg(&xd_hi[t4 + 4]);
        }

        float acc[4][HEADS];   // [pair*2 + row-half][head]
#pragma unroll
        for (int r = 0; r < 4; r++)
#pragma unroll
            for (int h = 0; h < HEADS; h++) acc[r][h] = 0.f;

#pragma unroll 4
        for (int nt = 0; nt < 64; nt++) {
            const int h = nt >> 4;
            const __half* bp = sB + (nt * 8 + g) * BK + t4 * 2;
            const uint32_t b00 = *(const uint32_t*)(bp);
            const uint32_t b01 = *(const uint32_t*)(bp + 8);
            const uint32_t b10 = *(const uint32_t*)(bp + 16);
            const uint32_t b11 = *(const uint32_t*)(bp + 24);
            const uint32_t b20 = *(const uint32_t*)(bp + 32);
            const uint32_t b21 = *(const uint32_t*)(bp + 40);
            const float2 aw = *(const float2*)(satt + nt * 8 + t4 * 2);

#pragma unroll
            for (int p = 0; p < 2; p++) {
                float c[4] = {0.f, 0.f, 0.f, 0.f};
                mma16816(c, A[2 * p],     b00, b01);
                mma16816(c, A[2 * p + 1], b10, b11);
                mma16816(c, aC,           b20, b21);
                acc[2 * p][h]     = fmaf(lrelu(c[0]), aw.x,
                                    fmaf(lrelu(c[1]), aw.y, acc[2 * p][h]));
                acc[2 * p + 1][h] = fmaf(lrelu(c[2]), aw.x,
                                    fmaf(lrelu(c[3]), aw.y, acc[2 * p + 1][h]));
            }
        }

#pragma unroll
        for (int r = 0; r < 4; r++)
#pragma unroll
            for (int h = 0; h < HEADS; h++) {
                float v = acc[r][h];
                v += __shfl_xor_sync(0xffffffffu, v, 1);
                v += __shfl_xor_sync(0xffffffffu, v, 2);
                acc[r][h] = v;
            }

        if (t4 == 0) {
#pragma unroll
            for (int r = 0; r < 4; r++) {
                if (ec[r] < N_EDGES)
                    ((float4*)g_ex)[ec[r]] = make_float4(
                        __expf(acc[r][0]), __expf(acc[r][1]),
                        __expf(acc[r][2]), __expf(acc[r][3]));
            }
        }
    }
}

// ---------------------------------------------------------------------------
// K3: X-space aggregation. One warp per node; srcs batch-preloaded
// lane-parallel + shfl broadcast (breaks the per-edge dependent-load chain).
// ---------------------------------------------------------------------------
__global__ __launch_bounds__(256) void aggregate_kernel(const float* __restrict__ X)
{
    const int node = blockIdx.x * 8 + (threadIdx.x >> 5);
    if (node >= N_NODES) return;
    const int lane = threadIdx.x & 31;
    const int k = lane & 15;
    const int half = lane >> 4;
    const unsigned FULL = 0xffffffffu;

    const int eb = g_row[node];
    const int ee = g_row[node + 1];

    float yA = 0.f, yB = 0.f;             // heads: half and 2+half
    float4 den = make_float4(0.f, 0.f, 0.f, 0.f);

    for (int b = eb; b < ee; b += 32) {
        const int cnt = min(32, ee - b);
        int li = b + lane;
        if (li >= ee) li = eb;
        const int my_src = g_srcs[li];    // lane-parallel preload

        for (int j = 0; j < cnt; j++) {
            const int src = __shfl_sync(FULL, my_src, j);
            const float4 ex = __ldg(&((const float4*)g_ex)[b + j]);
            const float xv = __ldg(&X[(size_t)src * IN_DIM + k]);
            const float wA = half ? ex.y : ex.x;
            const float wB = half ? ex.w : ex.z;
            yA = fmaf(wA, xv, yA);
            yB = fmaf(wB, xv, yB);
            den.x += ex.x; den.y += ex.y; den.z += ex.z; den.w += ex.w;
        }
    }

    const float dA = half ? den.y : den.x;
    const float dB = half ? den.w : den.z;
    const float iA = (dA > 0.f) ? (1.0f / dA) : 0.f;
    const float iB = (dB > 0.f) ? (1.0f / dB) : 0.f;

    g_y[(size_t)node * 64 + lane]      = yA * iA;
    g_y[(size_t)node * 64 + 32 + lane] = yB * iB;
    if (lane < 4) {
        const float d = (lane == 0) ? den.x : (lane == 1) ? den.y
                      : (lane == 2) ? den.z : den.w;
        g_gate[node * HEADS + lane] = (d > 0.f) ? 1.f : 0.f;
    }
}

// ---------------------------------------------------------------------------
// K4: out[node] = y_norm[node] @ W_l + gate*b_l + bias. (unchanged)
// ---------------------------------------------------------------------------
__global__ __launch_bounds__(256) void outproj_kernel(
    const float* __restrict__ Wl, const float* __restrict__ bl,
    const float* __restrict__ bias, float* __restrict__ out)
{
    __shared__ float sy[128 * 64];   // 32 KB
    __shared__ float sg[128 * HEADS];
    const int c0 = threadIdx.x * 2;
    const int hh = c0 >> 7;

    unsigned long long w[IN_DIM];
#pragma unroll
    for (int k = 0; k < IN_DIM; k++)
        w[k] = pack2(Wl[k * HC + c0], Wl[k * HC + c0 + 1]);
    const float bl0 = bl[c0], bl1 = bl[c0 + 1];
    const float bs0 = bias[c0], bs1 = bias[c0 + 1];

    const int n0 = blockIdx.x * 128;
    const int nmax = min(128, N_NODES - n0);

    for (int i = threadIdx.x; i < nmax * 64; i += blockDim.x)
        sy[i] = g_y[(size_t)n0 * 64 + i];
    for (int i = threadIdx.x; i < nmax * HEADS; i += blockDim.x)
        sg[i] = g_gate[n0 * HEADS + i];
    __syncthreads();

    for (int n = 0; n < nmax; n++) {
        const float gate = sg[n * HEADS + hh];
        unsigned long long acc = pack2(fmaf(gate, bl0, bs0), fmaf(gate, bl1, bs1));
        const float* yrow = sy + n * 64 + hh * 16;
#pragma unroll
        for (int k = 0; k < IN_DIM; k++) {
            const float yv = yrow[k];
            ffma2(acc, pack2(yv, yv), w[k]);
        }
        float o0, o1;
        unpack2(acc, o0, o1);
        ((float2*)out)[((size_t)(n0 + n) * HC + c0) >> 1] = make_float2(o0, o1);
    }
}

// ---------------------------------------------------------------------------
extern "C" void kernel_launch(void* const* d_in, const int* in_sizes, int n_in,
                              void* d_out, int out_size)
{
    const float* X    = (const float*)d_in[0];  // [N, 16]
    const int*   idx  = (const int*)  d_in[1];  // [2, E]
    const float* Wl   = (const float*)d_in[2];  // [16, 512]
    const float* bl   = (const float*)d_in[3];  // [512]
    const float* Wr   = (const float*)d_in[4];  // [16, 512]
    const float* br   = (const float*)d_in[5];  // [512]
    const float* att  = (const float*)d_in[6];  // [4, 128]
    const float* bias = (const float*)d_in[7];  // [512]
    float* out = (float*)d_out;                 // [N, 512]

    void* counts_ptr = nullptr;
    cudaGetSymbolAddress(&counts_ptr, g_counts);
    cudaMemsetAsync(counts_ptr, 0, N_NODES * sizeof(int), 0);

    cudaFuncSetAttribute(tensor_score_kernel,
                         cudaFuncAttributeMaxDynamicSharedMemorySize, SMEM_TS);

    xcvt_kernel<<<(N_NODES * IN_DIM + 255) / 256, 256>>>(X);
    hist_kernel<<<(N_EDGES + 255) / 256, 256>>>(idx);
    scanA_kernel<<<N_CHUNKS, SCAN_CHUNK>>>();
    scanB_kernel<<<1, 512>>>();
    scanC_kernel<<<N_CHUNKS, SCAN_CHUNK>>>();
    fill_kernel<<<(N_EDGES + 255) / 256, 256>>>(idx);
    tensor_score_kernel<<<TS_GRID, TS_THREADS, SMEM_TS>>>(Wl, bl, Wr, br, att);
    aggregate_kernel<<<(N_NODES + 7) / 8, 256>>>(X);
    outproj_kernel<<<(N_NODES + 127) / 128, 256>>>(Wl, bl, bias, out);
}